// round 17
// baseline (speedup 1.0000x reference)
#include <cuda_runtime.h>
#include <cuda_fp16.h>
#include <math.h>
#include <stdint.h>
#include <string.h>

#define Gn 8
#define Hn 64
#define In 64
#define Bn 32
#define Tn 1000
#define XSTR (Gn * In)   // 512 floats per (b,t)
#define RS 16            // xq ring slots (steps)

// ---------------- packed f32x2 helpers (sm_103a) ----------------
__device__ __forceinline__ uint64_t ffma2(uint64_t a, uint64_t b, uint64_t c) {
    uint64_t d;
    asm("fma.rn.f32x2 %0, %1, %2, %3;" : "=l"(d) : "l"(a), "l"(b), "l"(c));
    return d;
}
__device__ __forceinline__ uint64_t fadd2(uint64_t a, uint64_t b) {
    uint64_t d;
    asm("add.rn.f32x2 %0, %1, %2;" : "=l"(d) : "l"(a), "l"(b));
    return d;
}
__device__ __forceinline__ float2 unpack2(uint64_t v) {
    float lo, hi;
    asm("mov.b64 {%0, %1}, %2;" : "=f"(lo), "=f"(hi) : "l"(v));
    return make_float2(lo, hi);
}
__device__ __forceinline__ float fsig(float x) {
    return __fdividef(1.f, 1.f + __expf(-x));
}
__device__ __forceinline__ uint32_t f2_h2(float lo, float hi) {
    __half2 h = __floats2half2_rn(lo, hi);
    uint32_t u;
    memcpy(&u, &h, 4);
    return u;
}

// Three 32-wide partial dots (one K-half of rows r,z,n), ONE vector read.
// wr/wz/wn: 8 ulonglong2 (32 floats each). 48 ffma2, 6 chains of depth 8.
__device__ __forceinline__ float3 dot32x3(const ulonglong2* wr, const ulonglong2* wz,
                                          const ulonglong2* wn, const float* v) {
    const ulonglong2* v2 = (const ulonglong2*)v;
    uint64_t r0 = 0ull, r1 = 0ull;
    uint64_t z0 = 0ull, z1 = 0ull;
    uint64_t n0 = 0ull, n1 = 0ull;
#pragma unroll
    for (int q = 0; q < 8; q++) {
        ulonglong2 hv = v2[q];
        r0 = ffma2(wr[q].x, hv.x, r0);
        r1 = ffma2(wr[q].y, hv.y, r1);
        z0 = ffma2(wz[q].x, hv.x, z0);
        z1 = ffma2(wz[q].y, hv.y, z1);
        n0 = ffma2(wn[q].x, hv.x, n0);
        n1 = ffma2(wn[q].y, hv.y, n1);
    }
    float2 fr = unpack2(fadd2(r0, r1));
    float2 fz = unpack2(fadd2(z0, z1));
    float2 fn = unpack2(fadd2(n0, n1));
    return make_float3(fr.x + fr.y, fz.x + fz.y, fn.x + fn.y);
}

__device__ __forceinline__ void mma_16x8x16(float& d0, float& d1, float& d2, float& d3,
                                            uint32_t a0, uint32_t a1, uint32_t a2, uint32_t a3,
                                            uint32_t b0, uint32_t b1) {
    asm volatile(
        "mma.sync.aligned.m16n8k16.row.col.f32.f16.f16.f32 "
        "{%0,%1,%2,%3}, {%4,%5,%6,%7}, {%8,%9}, {%0,%1,%2,%3};"
        : "+f"(d0), "+f"(d1), "+f"(d2), "+f"(d3)
        : "r"(a0), "r"(a1), "r"(a2), "r"(a3), "r"(b0), "r"(b1));
}

__device__ __forceinline__ void named_bar(int id, int cnt) {
    asm volatile("bar.sync %0, %1;" :: "r"(id), "r"(cnt) : "memory");
}

// ---------------------------------------------------------------------------
// One block = TWO instances; grid = 128 (1 block/SM), 384 threads.
//  tid   0..127: scan inst0 (4 warps; lane pair (2e,2e+1) owns K-halves
//                of Whh rows {e,64+e,128+e}; shfl_xor(1) combines)
//  tid 128..255: scan inst1
//  tid 256..319: prod inst0 (HMMA xproj, R16 design)
//  tid 320..383: prod inst1
// Each SMSP: 2 scan warps + 1 producer warp.
// ---------------------------------------------------------------------------
__global__ void __launch_bounds__(384, 1) gru_kernel(
    const float* __restrict__ x,
    const float* __restrict__ h0,
    const float* __restrict__ Wih,
    const float* __restrict__ Whh,
    const float* __restrict__ bih,
    const float* __restrict__ bhh,
    float* __restrict__ out)
{
    const int tid = threadIdx.x;
    const bool is_prod = (tid >= 256);
    const int inst = is_prod ? ((tid - 256) >> 6) : (tid >> 7);
    const int bg   = 2 * blockIdx.x + inst;
    const int b    = bg >> 3;
    const int g    = bg & 7;

    __shared__ __align__(16) float xq[2][RS][192];  // per-inst xp ring
    __shared__ __align__(16) float hbuf[2][2][64];  // per-inst dbl-buffered h
    __shared__ int prodc[2];
    __shared__ int consc[2];

    if (tid < 2) { prodc[tid] = 0; consc[tid] = 0; }
    __syncthreads();

    volatile int* vprod = (volatile int*)&prodc[inst];
    volatile int* vcons = (volatile int*)&consc[inst];

    if (is_prod) {
        // ====================== PRODUCER (tensor core, R16) ======================
        const int pe    = (tid - 256) & 63;
        const int pw    = pe >> 5;          // warp within instance
        const int lane  = tid & 31;
        const int gid   = lane >> 2;        // 0..7 (timestep within group)
        const int t4    = lane & 3;
        const int rbase = pw * 96;
        const int barid = 3 + inst;

        uint32_t A[6][4][4];
        float bA[6], bB[6];
#pragma unroll
        for (int mt = 0; mt < 6; mt++) {
            const int r0 = rbase + mt * 16 + gid;
            const int r1 = r0 + 8;
            bA[mt] = bih[g * 192 + r0];
            bB[mt] = bih[g * 192 + r1];
#pragma unroll
            for (int kt = 0; kt < 4; kt++) {
                const int c0 = kt * 16 + 2 * t4;
                float2 w00 = *(const float2*)&Wih[((size_t)g * 192 + r0) * In + c0];
                float2 w10 = *(const float2*)&Wih[((size_t)g * 192 + r1) * In + c0];
                float2 w01 = *(const float2*)&Wih[((size_t)g * 192 + r0) * In + c0 + 8];
                float2 w11 = *(const float2*)&Wih[((size_t)g * 192 + r1) * In + c0 + 8];
                A[mt][kt][0] = f2_h2(w00.x, w00.y);
                A[mt][kt][1] = f2_h2(w10.x, w10.y);
                A[mt][kt][2] = f2_h2(w01.x, w01.y);
                A[mt][kt][3] = f2_h2(w11.x, w11.y);
            }
        }

        const float* xsrc = x + ((size_t)b * Tn) * XSTR + g * In;

        for (int p = 0; p < Tn / 8; p++) {
            const int lim = 8 * p - 8;
            if (lim > 0) { while (*vcons < lim) {} }

            const float* xg = xsrc + (size_t)(8 * p + gid) * XSTR;
            uint32_t Bf[4][2];
#pragma unroll
            for (int kt = 0; kt < 4; kt++) {
                const int k0 = kt * 16 + 2 * t4;
                float2 v0 = *(const float2*)&xg[k0];
                float2 v1 = *(const float2*)&xg[k0 + 8];
                Bf[kt][0] = f2_h2(v0.x, v0.y);
                Bf[kt][1] = f2_h2(v1.x, v1.y);
            }

            const int sb = (8 * p) & (RS - 1);
            float* ring = xq[inst][0];
#pragma unroll
            for (int mt = 0; mt < 6; mt++) {
                float d0 = bA[mt], d1 = bA[mt], d2 = bB[mt], d3 = bB[mt];
#pragma unroll
                for (int kt = 0; kt < 4; kt++)
                    mma_16x8x16(d0, d1, d2, d3,
                                A[mt][kt][0], A[mt][kt][1], A[mt][kt][2], A[mt][kt][3],
                                Bf[kt][0], Bf[kt][1]);
                const int r0 = rbase + mt * 16 + gid;
                const int s0 = sb + 2 * t4;
                ring[(size_t)s0 * 192 + r0]           = d0;
                ring[(size_t)(s0 + 1) * 192 + r0]     = d1;
                ring[(size_t)s0 * 192 + r0 + 8]       = d2;
                ring[(size_t)(s0 + 1) * 192 + r0 + 8] = d3;
            }
            __threadfence_block();
            named_bar(barid, 64);
            if (pe == 0) *vprod = 8 * p + 8;
        }
        return;
    }

    // ============================== SCAN (fp32, lane-pair split) ==============================
    const int ti    = tid & 127;
    const int e     = ti >> 1;    // element 0..63
    const int half  = ti & 1;     // K-half
    const int barid = 1 + inst;

    ulonglong2 wr[8], wz[8], wn[8];
    {
        const ulonglong2* p;
        p = (const ulonglong2*)&Whh[((size_t)g * 192 + e) * Hn + half * 32];
#pragma unroll
        for (int q = 0; q < 8; q++) wr[q] = p[q];
        p = (const ulonglong2*)&Whh[((size_t)g * 192 + 64 + e) * Hn + half * 32];
#pragma unroll
        for (int q = 0; q < 8; q++) wz[q] = p[q];
        p = (const ulonglong2*)&Whh[((size_t)g * 192 + 128 + e) * Hn + half * 32];
#pragma unroll
        for (int q = 0; q < 8; q++) wn[q] = p[q];
    }
    const float br = bhh[g * 192 + e];
    const float bz = bhh[g * 192 + 64 + e];
    const float bn = bhh[g * 192 + 128 + e];

    float hreg = h0[((size_t)g * Bn + b) * Hn + e];
    if (half == 0) hbuf[inst][0][e] = hreg;
    float* outp = out + (size_t)b * Tn * (Gn * Hn) + g * Hn + e;

    named_bar(barid, 128);   // hbuf[0] visible to all scan warps

    for (int t = 0; t < Tn; t++) {
        if ((t & 3) == 0) {
            if (ti == 0) *vcons = t;
            const int need = (t + 4 < Tn) ? (t + 4) : Tn;
            while (*vprod < need) {}
            __threadfence_block();
        }

        // xq loads issued BEFORE the dot (LDS latency hides under FFMA2)
        const float* slot = xq[inst][t & (RS - 1)];
        const float xr = slot[e];
        const float xz = slot[64 + e];
        const float xn = slot[128 + e];

        float3 d = dot32x3(wr, wz, wn, &hbuf[inst][t & 1][half * 32]);
        float vr = d.x + __shfl_xor_sync(0xFFFFFFFFu, d.x, 1);
        float vz = d.y + __shfl_xor_sync(0xFFFFFFFFu, d.y, 1);
        float vn = d.z + __shfl_xor_sync(0xFFFFFFFFu, d.z, 1);

        float rr = fsig(xr + (br + vr));
        float zz = fsig(xz + (bz + vz));
        float aa = xn + rr * (bn + vn);
        float nn = __fmaf_rn(2.f, fsig(2.f * aa), -1.f);
        float hn = nn + zz * (hreg - nn);
        hreg = hn;
        if (half == 0) {
            hbuf[inst][(t + 1) & 1][e] = hn;
            __stcs(&outp[(size_t)t * (Gn * Hn)], hn);
        }

        named_bar(barid, 128);   // h(t) writes ordered before h(t+1) reads
    }

    if (half == 0) {
        out[(size_t)Bn * Tn * (Gn * Hn) + ((size_t)g * Bn + b) * Hn + e] = hreg;
    }
}

// ---------------------------------------------------------------------------
extern "C" void kernel_launch(void* const* d_in, const int* in_sizes, int n_in,
                              void* d_out, int out_size)
{
    const float* x   = (const float*)d_in[0];
    const float* h0  = (const float*)d_in[1];
    const float* Wih = (const float*)d_in[2];
    const float* Whh = (const float*)d_in[3];
    const float* bih = (const float*)d_in[4];
    const float* bhh = (const float*)d_in[5];
    float* out = (float*)d_out;

    gru_kernel<<<(Bn * Gn) / 2, 384>>>(x, h0, Wih, Whh, bih, bhh, out);
}